// round 10
// baseline (speedup 1.0000x reference)
#include <cuda_runtime.h>

// Fused upsample2x-bilinear -> affine_grid -> grid_sample_bilinear.
// Separable composition: output = 3x3 weighted sum over ORIGINAL image.
// R10: R9 structure; issue-slimmed inner loop: tap temps zero-initialized
// ONCE (stale finite values are safe under w==0 since fma(0,v,acc)=acc),
// v2.b64 predicated loads, and packed fma.rn.f32x2 (FFMA2) accumulation.

#define N_   8
#define C_   32
#define HI   256
#define WI   256
#define HU   512
#define WU   512

// NHWC scratch: 8*256*256*32 floats = 67 MB (device global: allocation-free)
__device__ float4 g_nhwc4[N_ * HI * WI * (C_ / 4)];

// ---------------- prepass: NCHW -> NHWC tiled transpose ----------------
__global__ void __launch_bounds__(256)
transpose_nhwc(const float* __restrict__ x) {
    __shared__ float t[C_][33];
    int lane = threadIdx.x & 31;
    int wp   = threadIdx.x >> 5;          // 8 warps
    int bh = blockIdx.x;                   // n*HI + h
    int w0 = blockIdx.y << 5;              // w tile origin (8 tiles)
    int n = bh >> 8, h = bh & 255;

    const float* ip = x + (((long long)n * C_) * HI + h) * WI + w0;
    #pragma unroll
    for (int k = 0; k < 4; k++) {
        int c = (k << 3) + wp;
        t[c][lane] = ip[(long long)c * (HI * WI) + lane];   // coalesced read
    }
    __syncthreads();

    float* op = (float*)g_nhwc4 + (((long long)n * HI + h) * WI + w0) * C_;
    #pragma unroll
    for (int k = 0; k < 4; k++) {
        int wl = (k << 3) + wp;
        op[wl * C_ + lane] = t[lane][wl];                   // coalesced write
    }
}

// ---------------- main fused kernel ----------------
__device__ __forceinline__ void axis_taps(float f, int U, int O,
                                          int& base, float w[3]) {
    float f0 = floorf(f);
    int   i0 = (int)f0;
    float wf = f - f0;

    w[0] = 0.f; w[1] = 0.f; w[2] = 0.f;
    base = 0;

    #pragma unroll
    for (int k = 0; k < 2; k++) {
        int   t  = i0 + k;
        float Wk = (k == 0) ? (1.0f - wf) : wf;
        Wk = (t >= 0 && t < U) ? Wk : 0.0f;          // zero-padding validity
        int tc = min(max(t, 0), U - 1);
        float s  = fmaxf((float)tc * 0.5f - 0.25f, 0.0f);  // upsample source
        int   o0 = (int)s;
        float wu = s - (float)o0;
        int   o1 = min(o0 + 1, O - 1);
        if (k == 0) base = o0;                       // taps are monotone
        w[o0 - base] += Wk * (1.0f - wu);
        w[o1 - base] += Wk * wu;
    }
}

// Predicated 128-bit load into persistent (caller-initialized) temps.
// No memory request and temps keep prior finite value when w == 0.
__device__ __forceinline__ void pred_load2(unsigned long long& a,
                                           unsigned long long& b,
                                           const float4* addr, float w) {
    asm("{\n\t"
        ".reg .pred p;\n\t"
        "setp.ne.f32 p, %2, 0f00000000;\n\t"
        "@p ld.global.nc.v2.b64 {%0, %1}, [%3];\n\t"
        "}"
        : "+l"(a), "+l"(b)
        : "f"(w), "l"((const void*)addr));
}

#define PACK2(d, s)   asm("mov.b64 %0, {%1, %1};" : "=l"(d) : "f"(s))
#define FMA2(acc, t, w2) \
    asm("fma.rn.f32x2 %0, %1, %2, %0;" : "+l"(acc) : "l"(t), "l"(w2))
#define UNPACK2(lo, hi, s) \
    asm("mov.b64 {%0, %1}, %2;" : "=f"(lo), "=f"(hi) : "l"(s))

__global__ void __launch_bounds__(256, 3)
fused_gather_nhwc(const float* __restrict__ theta,
                  float* __restrict__ out) {
    __shared__ float obuf[8][C_][33];   // [warp][channel][point], pad 33

    const unsigned FULL = 0xFFFFFFFFu;
    int w    = threadIdx.x >> 5;
    int lane = threadIdx.x & 31;
    int wid  = blockIdx.x * 8 + w;
    int n   = wid >> 13;                 // 8192 warps per image
    int r   = wid & 8191;
    int yo  = r >> 4;                    // 512 rows
    int xo0 = (r & 15) << 5;             // 16 x-segments of 32

    float* outp = out + ((long long)n * C_) * (HU * WU)
                      + (long long)yo * WU + xo0;

    // ---- per-lane taps for point (xo0+lane, yo) ----
    int ro4[3], co4[3];
    float wy[3], wx[3];
    int z;                               // 1 if this point contributes zero
    {
        int xo = xo0 + lane;
        float gxn = (2.0f * (float)xo + 1.0f) / (float)WU - 1.0f;
        float gyn = (2.0f * (float)yo + 1.0f) / (float)HU - 1.0f;
        const float* th = theta + n * 6;
        float gox = __ldg(th + 0) * gxn + __ldg(th + 1) * gyn + __ldg(th + 2);
        float goy = __ldg(th + 3) * gxn + __ldg(th + 4) * gyn + __ldg(th + 5);
        float ix = ((gox + 1.0f) * (float)WU - 1.0f) * 0.5f;
        float iy = ((goy + 1.0f) * (float)HU - 1.0f) * 0.5f;

        int by, bx;
        axis_taps(iy, HU, HI, by, wy);   // indices always clamped into range
        axis_taps(ix, WU, WI, bx, wx);

        #pragma unroll
        for (int i = 0; i < 3; i++) {
            ro4[i] = min(by + i, HI - 1) * (WI * (C_ / 4));  // float4 units
            co4[i] = min(bx + i, WI - 1) * (C_ / 4);
        }
        z = ((wy[0] + wy[1] + wy[2]) == 0.0f) ||
            ((wx[0] + wx[1] + wx[2]) == 0.0f);
    }

    // ---- whole warp out of bounds: direct zero stores (STG.128) ----
    if (__all_sync(FULL, z)) {
        float4 zv = make_float4(0.f, 0.f, 0.f, 0.f);
        #pragma unroll
        for (int k = 0; k < 8; k++) {
            int c = (k << 2) | (lane >> 3);
            int piece = lane & 7;
            *(float4*)(outp + (long long)c * (HU * WU) + (piece << 2)) = zv;
        }
        return;
    }

    // ---- 8 passes of 4 points x 32 channels ----
    int g  = lane >> 3;                  // point within pass
    int lc = lane & 7;                   // channel quad
    const float4* xp = g_nhwc4 + (long long)n * (HI * WI * (C_ / 4)) + lc;

    // Tap temps: zero-initialized ONCE. After a skipped load they hold the
    // previous pass's finite value; fma with w==0 contributes exactly 0.
    unsigned long long t[18];
    #pragma unroll
    for (int k = 0; k < 18; k++) t[k] = 0ull;

    for (int pass = 0; pass < 8; pass++) {
        int src = (pass << 2) | g;
        int R0 = __shfl_sync(FULL, ro4[0], src);
        int R1 = __shfl_sync(FULL, ro4[1], src);
        int R2 = __shfl_sync(FULL, ro4[2], src);
        int K0 = __shfl_sync(FULL, co4[0], src);
        int K1 = __shfl_sync(FULL, co4[1], src);
        int K2 = __shfl_sync(FULL, co4[2], src);
        float Y0 = __shfl_sync(FULL, wy[0], src);
        float Y1 = __shfl_sync(FULL, wy[1], src);
        float Y2 = __shfl_sync(FULL, wy[2], src);
        float X0 = __shfl_sync(FULL, wx[0], src);
        float X1 = __shfl_sync(FULL, wx[1], src);
        float X2 = __shfl_sync(FULL, wx[2], src);

        float wij[9];
        wij[0] = Y0 * X0; wij[1] = Y0 * X1; wij[2] = Y0 * X2;
        wij[3] = Y1 * X0; wij[4] = Y1 * X1; wij[5] = Y1 * X2;
        wij[6] = Y2 * X0; wij[7] = Y2 * X1; wij[8] = Y2 * X2;

        // 9 predicated 128-bit loads issued back-to-back (high MLP)
        pred_load2(t[0],  t[1],  xp + R0 + K0, wij[0]);
        pred_load2(t[2],  t[3],  xp + R0 + K1, wij[1]);
        pred_load2(t[4],  t[5],  xp + R0 + K2, wij[2]);
        pred_load2(t[6],  t[7],  xp + R1 + K0, wij[3]);
        pred_load2(t[8],  t[9],  xp + R1 + K1, wij[4]);
        pred_load2(t[10], t[11], xp + R1 + K2, wij[5]);
        pred_load2(t[12], t[13], xp + R2 + K0, wij[6]);
        pred_load2(t[14], t[15], xp + R2 + K1, wij[7]);
        pred_load2(t[16], t[17], xp + R2 + K2, wij[8]);

        unsigned long long acc01 = 0ull, acc23 = 0ull;
        #pragma unroll
        for (int k = 0; k < 9; k++) {
            unsigned long long w2;
            PACK2(w2, wij[k]);
            FMA2(acc01, t[2 * k],     w2);
            FMA2(acc23, t[2 * k + 1], w2);
        }

        float ax, ay, az, aw;
        UNPACK2(ax, ay, acc01);
        UNPACK2(az, aw, acc23);

        int p  = (pass << 2) | g;
        int cb = lc << 2;
        obuf[w][cb + 0][p] = ax;         // bank = (4lc+g)+const: conflict-free
        obuf[w][cb + 1][p] = ay;
        obuf[w][cb + 2][p] = az;
        obuf[w][cb + 3][p] = aw;
    }
    __syncwarp();

    // ---- NCHW stores: 8 x STG.128 (4 channel-rows / instruction) ----
    #pragma unroll
    for (int k = 0; k < 8; k++) {
        int c = (k << 2) | (lane >> 3);
        int piece = lane & 7;
        float4 v;
        v.x = obuf[w][c][(piece << 2) + 0];   // banks distinct across lanes
        v.y = obuf[w][c][(piece << 2) + 1];
        v.z = obuf[w][c][(piece << 2) + 2];
        v.w = obuf[w][c][(piece << 2) + 3];
        *(float4*)(outp + (long long)c * (HU * WU) + (piece << 2)) = v;
    }
}

extern "C" void kernel_launch(void* const* d_in, const int* in_sizes, int n_in,
                              void* d_out, int out_size) {
    const float* x     = (const float*)d_in[0];
    const float* theta = (const float*)d_in[1];
    float*       out   = (float*)d_out;

    dim3 tg(N_ * HI, WI / 32);           // (2048, 8) tiles of 32c x 32w
    transpose_nhwc<<<tg, 256>>>(x);

    // 65536 warps: one warp per 32-point output row segment (all 32 channels)
    fused_gather_nhwc<<<8192, 256>>>(theta, out);
}

// round 11
// speedup vs baseline: 1.0370x; 1.0370x over previous
#include <cuda_runtime.h>

// Fused upsample2x-bilinear -> affine_grid -> grid_sample_bilinear.
// Separable composition: output = 3x3 weighted sum over ORIGINAL image.
// R11: R9 memory structure (per-pass fresh predicated loads, full MLP) +
// R10 issue diet (b64 zero-init pairs, packed fma.rn.f32x2 accumulation).

#define N_   8
#define C_   32
#define HI   256
#define WI   256
#define HU   512
#define WU   512

// NHWC scratch: 8*256*256*32 floats = 67 MB (device global: allocation-free)
__device__ float4 g_nhwc4[N_ * HI * WI * (C_ / 4)];

// ---------------- prepass: NCHW -> NHWC tiled transpose ----------------
__global__ void __launch_bounds__(256)
transpose_nhwc(const float* __restrict__ x) {
    __shared__ float t[C_][33];
    int lane = threadIdx.x & 31;
    int wp   = threadIdx.x >> 5;          // 8 warps
    int bh = blockIdx.x;                   // n*HI + h
    int w0 = blockIdx.y << 5;              // w tile origin (8 tiles)
    int n = bh >> 8, h = bh & 255;

    const float* ip = x + (((long long)n * C_) * HI + h) * WI + w0;
    #pragma unroll
    for (int k = 0; k < 4; k++) {
        int c = (k << 3) + wp;
        t[c][lane] = ip[(long long)c * (HI * WI) + lane];   // coalesced read
    }
    __syncthreads();

    float* op = (float*)g_nhwc4 + (((long long)n * HI + h) * WI + w0) * C_;
    #pragma unroll
    for (int k = 0; k < 4; k++) {
        int wl = (k << 3) + wp;
        op[wl * C_ + lane] = t[lane][wl];                   // coalesced write
    }
}

// ---------------- main fused kernel ----------------
__device__ __forceinline__ void axis_taps(float f, int U, int O,
                                          int& base, float w[3]) {
    float f0 = floorf(f);
    int   i0 = (int)f0;
    float wf = f - f0;

    w[0] = 0.f; w[1] = 0.f; w[2] = 0.f;
    base = 0;

    #pragma unroll
    for (int k = 0; k < 2; k++) {
        int   t  = i0 + k;
        float Wk = (k == 0) ? (1.0f - wf) : wf;
        Wk = (t >= 0 && t < U) ? Wk : 0.0f;          // zero-padding validity
        int tc = min(max(t, 0), U - 1);
        float s  = fmaxf((float)tc * 0.5f - 0.25f, 0.0f);  // upsample source
        int   o0 = (int)s;
        float wu = s - (float)o0;
        int   o1 = min(o0 + 1, O - 1);
        if (k == 0) base = o0;                       // taps are monotone
        w[o0 - base] += Wk * (1.0f - wu);
        w[o1 - base] += Wk * wu;
    }
}

// Predicated 128-bit load into FRESH zero-init b64 pair (2 movs).
// No memory request when w == 0; fma with w==0 contributes exactly 0.
__device__ __forceinline__ void pred_load2(unsigned long long& a,
                                           unsigned long long& b,
                                           const float4* addr, float w) {
    asm("{\n\t"
        ".reg .pred p;\n\t"
        "setp.ne.f32 p, %2, 0f00000000;\n\t"
        "mov.b64 %0, 0;\n\t"
        "mov.b64 %1, 0;\n\t"
        "@p ld.global.nc.v2.b64 {%0, %1}, [%3];\n\t"
        "}"
        : "=l"(a), "=l"(b)
        : "f"(w), "l"((const void*)addr));
}

#define PACK2(d, s)   asm("mov.b64 %0, {%1, %1};" : "=l"(d) : "f"(s))
#define FMA2(acc, t, w2) \
    asm("fma.rn.f32x2 %0, %1, %2, %0;" : "+l"(acc) : "l"(t), "l"(w2))
#define UNPACK2(lo, hi, s) \
    asm("mov.b64 {%0, %1}, %2;" : "=f"(lo), "=f"(hi) : "l"(s))

__global__ void __launch_bounds__(256, 3)
fused_gather_nhwc(const float* __restrict__ theta,
                  float* __restrict__ out) {
    __shared__ float obuf[8][C_][33];   // [warp][channel][point], pad 33

    const unsigned FULL = 0xFFFFFFFFu;
    int w    = threadIdx.x >> 5;
    int lane = threadIdx.x & 31;
    int wid  = blockIdx.x * 8 + w;
    int n   = wid >> 13;                 // 8192 warps per image
    int r   = wid & 8191;
    int yo  = r >> 4;                    // 512 rows
    int xo0 = (r & 15) << 5;             // 16 x-segments of 32

    float* outp = out + ((long long)n * C_) * (HU * WU)
                      + (long long)yo * WU + xo0;

    // ---- per-lane taps for point (xo0+lane, yo) ----
    int ro4[3], co4[3];
    float wy[3], wx[3];
    int z;                               // 1 if this point contributes zero
    {
        int xo = xo0 + lane;
        float gxn = (2.0f * (float)xo + 1.0f) / (float)WU - 1.0f;
        float gyn = (2.0f * (float)yo + 1.0f) / (float)HU - 1.0f;
        const float* th = theta + n * 6;
        float gox = __ldg(th + 0) * gxn + __ldg(th + 1) * gyn + __ldg(th + 2);
        float goy = __ldg(th + 3) * gxn + __ldg(th + 4) * gyn + __ldg(th + 5);
        float ix = ((gox + 1.0f) * (float)WU - 1.0f) * 0.5f;
        float iy = ((goy + 1.0f) * (float)HU - 1.0f) * 0.5f;

        int by, bx;
        axis_taps(iy, HU, HI, by, wy);   // indices always clamped into range
        axis_taps(ix, WU, WI, bx, wx);

        #pragma unroll
        for (int i = 0; i < 3; i++) {
            ro4[i] = min(by + i, HI - 1) * (WI * (C_ / 4));  // float4 units
            co4[i] = min(bx + i, WI - 1) * (C_ / 4);
        }
        z = ((wy[0] + wy[1] + wy[2]) == 0.0f) ||
            ((wx[0] + wx[1] + wx[2]) == 0.0f);
    }

    // ---- whole warp out of bounds: direct zero stores (STG.128) ----
    if (__all_sync(FULL, z)) {
        float4 zv = make_float4(0.f, 0.f, 0.f, 0.f);
        #pragma unroll
        for (int k = 0; k < 8; k++) {
            int c = (k << 2) | (lane >> 3);
            int piece = lane & 7;
            *(float4*)(outp + (long long)c * (HU * WU) + (piece << 2)) = zv;
        }
        return;
    }

    // ---- 8 passes of 4 points x 32 channels ----
    int g  = lane >> 3;                  // point within pass
    int lc = lane & 7;                   // channel quad
    const float4* xp = g_nhwc4 + (long long)n * (HI * WI * (C_ / 4)) + lc;

    for (int pass = 0; pass < 8; pass++) {
        int src = (pass << 2) | g;
        int R0 = __shfl_sync(FULL, ro4[0], src);
        int R1 = __shfl_sync(FULL, ro4[1], src);
        int R2 = __shfl_sync(FULL, ro4[2], src);
        int K0 = __shfl_sync(FULL, co4[0], src);
        int K1 = __shfl_sync(FULL, co4[1], src);
        int K2 = __shfl_sync(FULL, co4[2], src);
        float Y0 = __shfl_sync(FULL, wy[0], src);
        float Y1 = __shfl_sync(FULL, wy[1], src);
        float Y2 = __shfl_sync(FULL, wy[2], src);
        float X0 = __shfl_sync(FULL, wx[0], src);
        float X1 = __shfl_sync(FULL, wx[1], src);
        float X2 = __shfl_sync(FULL, wx[2], src);

        float wij[9];
        wij[0] = Y0 * X0; wij[1] = Y0 * X1; wij[2] = Y0 * X2;
        wij[3] = Y1 * X0; wij[4] = Y1 * X1; wij[5] = Y1 * X2;
        wij[6] = Y2 * X0; wij[7] = Y2 * X1; wij[8] = Y2 * X2;

        // 9 predicated 128-bit loads, fresh temps, issued back-to-back
        unsigned long long t[18];
        pred_load2(t[0],  t[1],  xp + R0 + K0, wij[0]);
        pred_load2(t[2],  t[3],  xp + R0 + K1, wij[1]);
        pred_load2(t[4],  t[5],  xp + R0 + K2, wij[2]);
        pred_load2(t[6],  t[7],  xp + R1 + K0, wij[3]);
        pred_load2(t[8],  t[9],  xp + R1 + K1, wij[4]);
        pred_load2(t[10], t[11], xp + R1 + K2, wij[5]);
        pred_load2(t[12], t[13], xp + R2 + K0, wij[6]);
        pred_load2(t[14], t[15], xp + R2 + K1, wij[7]);
        pred_load2(t[16], t[17], xp + R2 + K2, wij[8]);

        unsigned long long acc01 = 0ull, acc23 = 0ull;
        #pragma unroll
        for (int k = 0; k < 9; k++) {
            unsigned long long w2;
            PACK2(w2, wij[k]);
            FMA2(acc01, t[2 * k],     w2);
            FMA2(acc23, t[2 * k + 1], w2);
        }

        float ax, ay, az, aw;
        UNPACK2(ax, ay, acc01);
        UNPACK2(az, aw, acc23);

        int p  = (pass << 2) | g;
        int cb = lc << 2;
        obuf[w][cb + 0][p] = ax;         // bank = (4lc+g)+const: conflict-free
        obuf[w][cb + 1][p] = ay;
        obuf[w][cb + 2][p] = az;
        obuf[w][cb + 3][p] = aw;
    }
    __syncwarp();

    // ---- NCHW stores: 8 x STG.128 (4 channel-rows / instruction) ----
    #pragma unroll
    for (int k = 0; k < 8; k++) {
        int c = (k << 2) | (lane >> 3);
        int piece = lane & 7;
        float4 v;
        v.x = obuf[w][c][(piece << 2) + 0];   // banks distinct across lanes
        v.y = obuf[w][c][(piece << 2) + 1];
        v.z = obuf[w][c][(piece << 2) + 2];
        v.w = obuf[w][c][(piece << 2) + 3];
        *(float4*)(outp + (long long)c * (HU * WU) + (piece << 2)) = v;
    }
}

extern "C" void kernel_launch(void* const* d_in, const int* in_sizes, int n_in,
                              void* d_out, int out_size) {
    const float* x     = (const float*)d_in[0];
    const float* theta = (const float*)d_in[1];
    float*       out   = (float*)d_out;

    dim3 tg(N_ * HI, WI / 32);           // (2048, 8) tiles of 32c x 32w
    transpose_nhwc<<<tg, 256>>>(x);

    // 65536 warps: one warp per 32-point output row segment (all 32 channels)
    fused_gather_nhwc<<<8192, 256>>>(theta, out);
}

// round 12
// speedup vs baseline: 1.0601x; 1.0223x over previous
#include <cuda_runtime.h>

// Fused upsample2x-bilinear -> affine_grid -> grid_sample_bilinear.
// Separable composition: output = 3x3 weighted sum over ORIGINAL image.
// R12: R11 minus shuffle overhead. y-taps are warp-uniform (hoisted to
// registers, zero per-pass cost); x-taps staged in a per-warp SMEM table
// read with 2 broadcast LDS.128 per pass instead of 6 SHFL.

#define N_   8
#define C_   32
#define HI   256
#define WI   256
#define HU   512
#define WU   512

// NHWC scratch: 8*256*256*32 floats = 67 MB (device global: allocation-free)
__device__ float4 g_nhwc4[N_ * HI * WI * (C_ / 4)];

// ---------------- prepass: NCHW -> NHWC tiled transpose ----------------
__global__ void __launch_bounds__(256)
transpose_nhwc(const float* __restrict__ x) {
    __shared__ float t[C_][33];
    int lane = threadIdx.x & 31;
    int wp   = threadIdx.x >> 5;          // 8 warps
    int bh = blockIdx.x;                   // n*HI + h
    int w0 = blockIdx.y << 5;              // w tile origin (8 tiles)
    int n = bh >> 8, h = bh & 255;

    const float* ip = x + (((long long)n * C_) * HI + h) * WI + w0;
    #pragma unroll
    for (int k = 0; k < 4; k++) {
        int c = (k << 3) + wp;
        t[c][lane] = ip[(long long)c * (HI * WI) + lane];   // coalesced read
    }
    __syncthreads();

    float* op = (float*)g_nhwc4 + (((long long)n * HI + h) * WI + w0) * C_;
    #pragma unroll
    for (int k = 0; k < 4; k++) {
        int wl = (k << 3) + wp;
        op[wl * C_ + lane] = t[lane][wl];                   // coalesced write
    }
}

// ---------------- main fused kernel ----------------
__device__ __forceinline__ void axis_taps(float f, int U, int O,
                                          int& base, float w[3]) {
    float f0 = floorf(f);
    int   i0 = (int)f0;
    float wf = f - f0;

    w[0] = 0.f; w[1] = 0.f; w[2] = 0.f;
    base = 0;

    #pragma unroll
    for (int k = 0; k < 2; k++) {
        int   t  = i0 + k;
        float Wk = (k == 0) ? (1.0f - wf) : wf;
        Wk = (t >= 0 && t < U) ? Wk : 0.0f;          // zero-padding validity
        int tc = min(max(t, 0), U - 1);
        float s  = fmaxf((float)tc * 0.5f - 0.25f, 0.0f);  // upsample source
        int   o0 = (int)s;
        float wu = s - (float)o0;
        int   o1 = min(o0 + 1, O - 1);
        if (k == 0) base = o0;                       // taps are monotone
        w[o0 - base] += Wk * (1.0f - wu);
        w[o1 - base] += Wk * wu;
    }
}

// Predicated 128-bit load into FRESH zero-init b64 pair (2 movs).
// No memory request when w == 0; fma with w==0 contributes exactly 0.
__device__ __forceinline__ void pred_load2(unsigned long long& a,
                                           unsigned long long& b,
                                           const float4* addr, float w) {
    asm("{\n\t"
        ".reg .pred p;\n\t"
        "setp.ne.f32 p, %2, 0f00000000;\n\t"
        "mov.b64 %0, 0;\n\t"
        "mov.b64 %1, 0;\n\t"
        "@p ld.global.nc.v2.b64 {%0, %1}, [%3];\n\t"
        "}"
        : "=l"(a), "=l"(b)
        : "f"(w), "l"((const void*)addr));
}

#define PACK2(d, s)   asm("mov.b64 %0, {%1, %1};" : "=l"(d) : "f"(s))
#define FMA2(acc, t, w2) \
    asm("fma.rn.f32x2 %0, %1, %2, %0;" : "+l"(acc) : "l"(t), "l"(w2))
#define UNPACK2(lo, hi, s) \
    asm("mov.b64 {%0, %1}, %2;" : "=f"(lo), "=f"(hi) : "l"(s))

__global__ void __launch_bounds__(256, 3)
fused_gather_nhwc(const float* __restrict__ theta,
                  float* __restrict__ out) {
    __shared__ float  obuf[8][C_][33];  // [warp][channel][point], pad 33
    __shared__ float4 xw[8][32];        // per-point x weights
    __shared__ int4   xk[8][32];        // per-point x float4-offsets

    const unsigned FULL = 0xFFFFFFFFu;
    int w    = threadIdx.x >> 5;
    int lane = threadIdx.x & 31;
    int wid  = blockIdx.x * 8 + w;
    int n   = wid >> 13;                 // 8192 warps per image
    int r   = wid & 8191;
    int yo  = r >> 4;                    // 512 rows (warp-uniform)
    int xo0 = (r & 15) << 5;             // 16 x-segments of 32

    float* outp = out + ((long long)n * C_) * (HU * WU)
                      + (long long)yo * WU + xo0;

    const float* th = theta + n * 6;
    float t0 = __ldg(th + 0), t1 = __ldg(th + 1), t2 = __ldg(th + 2);
    float t3 = __ldg(th + 3), t4 = __ldg(th + 4), t5 = __ldg(th + 5);
    float gyn = (2.0f * (float)yo + 1.0f) / (float)HU - 1.0f;

    // ---- warp-uniform y taps (identical in every lane, kept in regs) ----
    float Y0, Y1, Y2;
    int   R0, R1, R2;
    int   zy;
    {
        // per-lane gyn-dependent only via uniform yo -> all lanes identical
        // iy depends on gox? no: iy uses goy which depends on gxn... CAREFUL:
        // goy = t3*gxn + t4*gyn + t5 depends on x! y taps are NOT uniform.
        // (handled below; this block intentionally left to per-lane code)
        Y0 = Y1 = Y2 = 0.f; R0 = R1 = R2 = 0; zy = 0;
        (void)zy;
    }

    // ---- per-lane taps for point (xo0+lane, yo) ----
    // NOTE: both ix and iy depend on the lane's xo (full affine), so each
    // lane computes BOTH axes for its own point; y data goes to SMEM too.
    int z;
    {
        int xo = xo0 + lane;
        float gxn = (2.0f * (float)xo + 1.0f) / (float)WU - 1.0f;
        float gox = t0 * gxn + t1 * gyn + t2;
        float goy = t3 * gxn + t4 * gyn + t5;
        float ix = ((gox + 1.0f) * (float)WU - 1.0f) * 0.5f;
        float iy = ((goy + 1.0f) * (float)HU - 1.0f) * 0.5f;

        int by, bx;
        float wy[3], wx[3];
        axis_taps(iy, HU, HI, by, wy);
        axis_taps(ix, WU, WI, bx, wx);

        xw[w][lane] = make_float4(wx[0], wx[1], wx[2], 0.f);
        xk[w][lane] = make_int4(min(bx,     WI - 1) * (C_ / 4),
                                min(bx + 1, WI - 1) * (C_ / 4),
                                min(bx + 2, WI - 1) * (C_ / 4), 0);
        // y data varies per lane (goy depends on gxn): stash in obuf rows? no,
        // broadcast per pass via SHFL as before — but ONLY the 6 y values.
        Y0 = wy[0]; Y1 = wy[1]; Y2 = wy[2];
        R0 = min(by,     HI - 1) * (WI * (C_ / 4));
        R1 = min(by + 1, HI - 1) * (WI * (C_ / 4));
        R2 = min(by + 2, HI - 1) * (WI * (C_ / 4));

        z = ((wy[0] + wy[1] + wy[2]) == 0.0f) ||
            ((wx[0] + wx[1] + wx[2]) == 0.0f);
    }
    __syncwarp();

    // ---- whole warp out of bounds: direct zero stores (STG.128) ----
    if (__all_sync(FULL, z)) {
        float4 zv = make_float4(0.f, 0.f, 0.f, 0.f);
        #pragma unroll
        for (int k = 0; k < 8; k++) {
            int c = (k << 2) | (lane >> 3);
            int piece = lane & 7;
            *(float4*)(outp + (long long)c * (HU * WU) + (piece << 2)) = zv;
        }
        return;
    }

    // ---- 8 passes of 4 points x 32 channels ----
    int g  = lane >> 3;                  // point within pass
    int lc = lane & 7;                   // channel quad
    const float4* xp = g_nhwc4 + (long long)n * (HI * WI * (C_ / 4)) + lc;

    for (int pass = 0; pass < 8; pass++) {
        int src = (pass << 2) | g;
        // x taps: 2 broadcast LDS.128 (replaces 6 SHFL)
        float4 W = xw[w][src];
        int4   K = xk[w][src];
        // y taps: 6 SHFL (vary per lane: goy depends on x through t3)
        float y0 = __shfl_sync(FULL, Y0, src);
        float y1 = __shfl_sync(FULL, Y1, src);
        float y2 = __shfl_sync(FULL, Y2, src);
        int   r0 = __shfl_sync(FULL, R0, src);
        int   r1 = __shfl_sync(FULL, R1, src);
        int   r2 = __shfl_sync(FULL, R2, src);

        float wij[9];
        wij[0] = y0 * W.x; wij[1] = y0 * W.y; wij[2] = y0 * W.z;
        wij[3] = y1 * W.x; wij[4] = y1 * W.y; wij[5] = y1 * W.z;
        wij[6] = y2 * W.x; wij[7] = y2 * W.y; wij[8] = y2 * W.z;

        // 9 predicated 128-bit loads, fresh temps, issued back-to-back
        unsigned long long t[18];
        pred_load2(t[0],  t[1],  xp + r0 + K.x, wij[0]);
        pred_load2(t[2],  t[3],  xp + r0 + K.y, wij[1]);
        pred_load2(t[4],  t[5],  xp + r0 + K.z, wij[2]);
        pred_load2(t[6],  t[7],  xp + r1 + K.x, wij[3]);
        pred_load2(t[8],  t[9],  xp + r1 + K.y, wij[4]);
        pred_load2(t[10], t[11], xp + r1 + K.z, wij[5]);
        pred_load2(t[12], t[13], xp + r2 + K.x, wij[6]);
        pred_load2(t[14], t[15], xp + r2 + K.y, wij[7]);
        pred_load2(t[16], t[17], xp + r2 + K.z, wij[8]);

        unsigned long long acc01 = 0ull, acc23 = 0ull;
        #pragma unroll
        for (int k = 0; k < 9; k++) {
            unsigned long long w2;
            PACK2(w2, wij[k]);
            FMA2(acc01, t[2 * k],     w2);
            FMA2(acc23, t[2 * k + 1], w2);
        }

        float ax, ay, az, aw;
        UNPACK2(ax, ay, acc01);
        UNPACK2(az, aw, acc23);

        int p  = (pass << 2) | g;
        int cb = lc << 2;
        obuf[w][cb + 0][p] = ax;         // bank = (4lc+g)+const: conflict-free
        obuf[w][cb + 1][p] = ay;
        obuf[w][cb + 2][p] = az;
        obuf[w][cb + 3][p] = aw;
    }
    __syncwarp();

    // ---- NCHW stores: 8 x STG.128 (4 channel-rows / instruction) ----
    #pragma unroll
    for (int k = 0; k < 8; k++) {
        int c = (k << 2) | (lane >> 3);
        int piece = lane & 7;
        float4 v;
        v.x = obuf[w][c][(piece << 2) + 0];   // banks distinct across lanes
        v.y = obuf[w][c][(piece << 2) + 1];
        v.z = obuf[w][c][(piece << 2) + 2];
        v.w = obuf[w][c][(piece << 2) + 3];
        *(float4*)(outp + (long long)c * (HU * WU) + (piece << 2)) = v;
    }
}

extern "C" void kernel_launch(void* const* d_in, const int* in_sizes, int n_in,
                              void* d_out, int out_size) {
    const float* x     = (const float*)d_in[0];
    const float* theta = (const float*)d_in[1];
    float*       out   = (float*)d_out;

    dim3 tg(N_ * HI, WI / 32);           // (2048, 8) tiles of 32c x 32w
    transpose_nhwc<<<tg, 256>>>(x);

    // 65536 warps: one warp per 32-point output row segment (all 32 channels)
    fused_gather_nhwc<<<8192, 256>>>(theta, out);
}

// round 13
// speedup vs baseline: 1.0771x; 1.0160x over previous
#include <cuda_runtime.h>

// Fused upsample2x-bilinear -> affine_grid -> grid_sample_bilinear.
// Separable composition: output = 3x3 weighted sum over ORIGINAL image.
// R13: R12 + register diet for occupancy: 9 tap loads issued in two waves
// (5 then 4) reusing temp registers (peak 10 b64 instead of 18), and
// __launch_bounds__(256,4) to double resident blocks.

#define N_   8
#define C_   32
#define HI   256
#define WI   256
#define HU   512
#define WU   512

// NHWC scratch: 8*256*256*32 floats = 67 MB (device global: allocation-free)
__device__ float4 g_nhwc4[N_ * HI * WI * (C_ / 4)];

// ---------------- prepass: NCHW -> NHWC tiled transpose ----------------
__global__ void __launch_bounds__(256)
transpose_nhwc(const float* __restrict__ x) {
    __shared__ float t[C_][33];
    int lane = threadIdx.x & 31;
    int wp   = threadIdx.x >> 5;          // 8 warps
    int bh = blockIdx.x;                   // n*HI + h
    int w0 = blockIdx.y << 5;              // w tile origin (8 tiles)
    int n = bh >> 8, h = bh & 255;

    const float* ip = x + (((long long)n * C_) * HI + h) * WI + w0;
    #pragma unroll
    for (int k = 0; k < 4; k++) {
        int c = (k << 3) + wp;
        t[c][lane] = ip[(long long)c * (HI * WI) + lane];   // coalesced read
    }
    __syncthreads();

    float* op = (float*)g_nhwc4 + (((long long)n * HI + h) * WI + w0) * C_;
    #pragma unroll
    for (int k = 0; k < 4; k++) {
        int wl = (k << 3) + wp;
        op[wl * C_ + lane] = t[lane][wl];                   // coalesced write
    }
}

// ---------------- main fused kernel ----------------
__device__ __forceinline__ void axis_taps(float f, int U, int O,
                                          int& base, float w[3]) {
    float f0 = floorf(f);
    int   i0 = (int)f0;
    float wf = f - f0;

    w[0] = 0.f; w[1] = 0.f; w[2] = 0.f;
    base = 0;

    #pragma unroll
    for (int k = 0; k < 2; k++) {
        int   t  = i0 + k;
        float Wk = (k == 0) ? (1.0f - wf) : wf;
        Wk = (t >= 0 && t < U) ? Wk : 0.0f;          // zero-padding validity
        int tc = min(max(t, 0), U - 1);
        float s  = fmaxf((float)tc * 0.5f - 0.25f, 0.0f);  // upsample source
        int   o0 = (int)s;
        float wu = s - (float)o0;
        int   o1 = min(o0 + 1, O - 1);
        if (k == 0) base = o0;                       // taps are monotone
        w[o0 - base] += Wk * (1.0f - wu);
        w[o1 - base] += Wk * wu;
    }
}

// Predicated 128-bit load into FRESH zero-init b64 pair (2 movs).
// No memory request when w == 0; fma with w==0 contributes exactly 0.
__device__ __forceinline__ void pred_load2(unsigned long long& a,
                                           unsigned long long& b,
                                           const float4* addr, float w) {
    asm("{\n\t"
        ".reg .pred p;\n\t"
        "setp.ne.f32 p, %2, 0f00000000;\n\t"
        "mov.b64 %0, 0;\n\t"
        "mov.b64 %1, 0;\n\t"
        "@p ld.global.nc.v2.b64 {%0, %1}, [%3];\n\t"
        "}"
        : "=l"(a), "=l"(b)
        : "f"(w), "l"((const void*)addr));
}

#define PACK2(d, s)   asm("mov.b64 %0, {%1, %1};" : "=l"(d) : "f"(s))
#define FMA2(acc, t, w2) \
    asm("fma.rn.f32x2 %0, %1, %2, %0;" : "+l"(acc) : "l"(t), "l"(w2))
#define UNPACK2(lo, hi, s) \
    asm("mov.b64 {%0, %1}, %2;" : "=f"(lo), "=f"(hi) : "l"(s))

__global__ void __launch_bounds__(256, 4)
fused_gather_nhwc(const float* __restrict__ theta,
                  float* __restrict__ out) {
    __shared__ float  obuf[8][C_][33];  // [warp][channel][point], pad 33
    __shared__ float4 xw[8][32];        // per-point x weights
    __shared__ int4   xk[8][32];        // per-point x float4-offsets

    const unsigned FULL = 0xFFFFFFFFu;
    int w    = threadIdx.x >> 5;
    int lane = threadIdx.x & 31;
    int wid  = blockIdx.x * 8 + w;
    int n   = wid >> 13;                 // 8192 warps per image
    int r   = wid & 8191;
    int yo  = r >> 4;                    // 512 rows
    int xo0 = (r & 15) << 5;             // 16 x-segments of 32

    float* outp = out + ((long long)n * C_) * (HU * WU)
                      + (long long)yo * WU + xo0;

    const float* th = theta + n * 6;
    float t0 = __ldg(th + 0), t1 = __ldg(th + 1), t2 = __ldg(th + 2);
    float t3 = __ldg(th + 3), t4 = __ldg(th + 4), t5 = __ldg(th + 5);
    float gyn = (2.0f * (float)yo + 1.0f) / (float)HU - 1.0f;

    // ---- per-lane taps for point (xo0+lane, yo) ----
    float Y0, Y1, Y2;
    int   R0, R1, R2;
    int   z;
    {
        int xo = xo0 + lane;
        float gxn = (2.0f * (float)xo + 1.0f) / (float)WU - 1.0f;
        float gox = t0 * gxn + t1 * gyn + t2;
        float goy = t3 * gxn + t4 * gyn + t5;
        float ix = ((gox + 1.0f) * (float)WU - 1.0f) * 0.5f;
        float iy = ((goy + 1.0f) * (float)HU - 1.0f) * 0.5f;

        int by, bx;
        float wy[3], wx[3];
        axis_taps(iy, HU, HI, by, wy);
        axis_taps(ix, WU, WI, bx, wx);

        xw[w][lane] = make_float4(wx[0], wx[1], wx[2], 0.f);
        xk[w][lane] = make_int4(min(bx,     WI - 1) * (C_ / 4),
                                min(bx + 1, WI - 1) * (C_ / 4),
                                min(bx + 2, WI - 1) * (C_ / 4), 0);
        Y0 = wy[0]; Y1 = wy[1]; Y2 = wy[2];
        R0 = min(by,     HI - 1) * (WI * (C_ / 4));
        R1 = min(by + 1, HI - 1) * (WI * (C_ / 4));
        R2 = min(by + 2, HI - 1) * (WI * (C_ / 4));

        z = ((wy[0] + wy[1] + wy[2]) == 0.0f) ||
            ((wx[0] + wx[1] + wx[2]) == 0.0f);
    }
    __syncwarp();

    // ---- whole warp out of bounds: direct zero stores (STG.128) ----
    if (__all_sync(FULL, z)) {
        float4 zv = make_float4(0.f, 0.f, 0.f, 0.f);
        #pragma unroll
        for (int k = 0; k < 8; k++) {
            int c = (k << 2) | (lane >> 3);
            int piece = lane & 7;
            *(float4*)(outp + (long long)c * (HU * WU) + (piece << 2)) = zv;
        }
        return;
    }

    // ---- 8 passes of 4 points x 32 channels ----
    int g  = lane >> 3;                  // point within pass
    int lc = lane & 7;                   // channel quad
    const float4* xp = g_nhwc4 + (long long)n * (HI * WI * (C_ / 4)) + lc;

    for (int pass = 0; pass < 8; pass++) {
        int src = (pass << 2) | g;
        // x taps: 2 broadcast LDS.128
        float4 W = xw[w][src];
        int4   K = xk[w][src];
        // y taps: 6 SHFL (vary per lane: goy depends on x through t3)
        float y0 = __shfl_sync(FULL, Y0, src);
        float y1 = __shfl_sync(FULL, Y1, src);
        float y2 = __shfl_sync(FULL, Y2, src);
        int   r0 = __shfl_sync(FULL, R0, src);
        int   r1 = __shfl_sync(FULL, R1, src);
        int   r2 = __shfl_sync(FULL, R2, src);

        float wij[9];
        wij[0] = y0 * W.x; wij[1] = y0 * W.y; wij[2] = y0 * W.z;
        wij[3] = y1 * W.x; wij[4] = y1 * W.y; wij[5] = y1 * W.z;
        wij[6] = y2 * W.x; wij[7] = y2 * W.y; wij[8] = y2 * W.z;

        unsigned long long acc01 = 0ull, acc23 = 0ull;
        unsigned long long t[10];

        // Wave 1: taps 0..4 (5 loads in flight), then FMA 0..4 in order
        pred_load2(t[0], t[1], xp + r0 + K.x, wij[0]);
        pred_load2(t[2], t[3], xp + r0 + K.y, wij[1]);
        pred_load2(t[4], t[5], xp + r0 + K.z, wij[2]);
        pred_load2(t[6], t[7], xp + r1 + K.x, wij[3]);
        pred_load2(t[8], t[9], xp + r1 + K.y, wij[4]);
        #pragma unroll
        for (int k = 0; k < 5; k++) {
            unsigned long long w2;
            PACK2(w2, wij[k]);
            FMA2(acc01, t[2 * k],     w2);
            FMA2(acc23, t[2 * k + 1], w2);
        }

        // Wave 2: taps 5..8 reuse t[0..7], then FMA 5..8 in order
        pred_load2(t[0], t[1], xp + r1 + K.z, wij[5]);
        pred_load2(t[2], t[3], xp + r2 + K.x, wij[6]);
        pred_load2(t[4], t[5], xp + r2 + K.y, wij[7]);
        pred_load2(t[6], t[7], xp + r2 + K.z, wij[8]);
        #pragma unroll
        for (int k = 0; k < 4; k++) {
            unsigned long long w2;
            PACK2(w2, wij[5 + k]);
            FMA2(acc01, t[2 * k],     w2);
            FMA2(acc23, t[2 * k + 1], w2);
        }

        float ax, ay, az, aw;
        UNPACK2(ax, ay, acc01);
        UNPACK2(az, aw, acc23);

        int p  = (pass << 2) | g;
        int cb = lc << 2;
        obuf[w][cb + 0][p] = ax;         // bank = (4lc+g)+const: conflict-free
        obuf[w][cb + 1][p] = ay;
        obuf[w][cb + 2][p] = az;
        obuf[w][cb + 3][p] = aw;
    }
    __syncwarp();

    // ---- NCHW stores: 8 x STG.128 (4 channel-rows / instruction) ----
    #pragma unroll
    for (int k = 0; k < 8; k++) {
        int c = (k << 2) | (lane >> 3);
        int piece = lane & 7;
        float4 v;
        v.x = obuf[w][c][(piece << 2) + 0];   // banks distinct across lanes
        v.y = obuf[w][c][(piece << 2) + 1];
        v.z = obuf[w][c][(piece << 2) + 2];
        v.w = obuf[w][c][(piece << 2) + 3];
        *(float4*)(outp + (long long)c * (HU * WU) + (piece << 2)) = v;
    }
}

extern "C" void kernel_launch(void* const* d_in, const int* in_sizes, int n_in,
                              void* d_out, int out_size) {
    const float* x     = (const float*)d_in[0];
    const float* theta = (const float*)d_in[1];
    float*       out   = (float*)d_out;

    dim3 tg(N_ * HI, WI / 32);           // (2048, 8) tiles of 32c x 32w
    transpose_nhwc<<<tg, 256>>>(x);

    // 65536 warps: one warp per 32-point output row segment (all 32 channels)
    fused_gather_nhwc<<<8192, 256>>>(theta, out);
}

// round 14
// speedup vs baseline: 1.1793x; 1.0949x over previous
#include <cuda_runtime.h>

// Fused upsample2x-bilinear -> affine_grid -> grid_sample_bilinear.
// Separable composition: output = 3x3 weighted sum over ORIGINAL image.
// R14: R13 + per-point tap tables in SMEM (9 combined weights + ro/co
// offsets, 20 words/point). Per pass: 5 broadcast LDS replace
// 2 LDS + 6 SHFL + 9 FMUL. Same FMA order -> bit-exact vs R13.

#define N_   8
#define C_   32
#define HI   256
#define WI   256
#define HU   512
#define WU   512

// NHWC scratch: 8*256*256*32 floats = 67 MB (device global: allocation-free)
__device__ float4 g_nhwc4[N_ * HI * WI * (C_ / 4)];

// ---------------- prepass: NCHW -> NHWC tiled transpose ----------------
__global__ void __launch_bounds__(256)
transpose_nhwc(const float* __restrict__ x) {
    __shared__ float t[C_][33];
    int lane = threadIdx.x & 31;
    int wp   = threadIdx.x >> 5;          // 8 warps
    int bh = blockIdx.x;                   // n*HI + h
    int w0 = blockIdx.y << 5;              // w tile origin (8 tiles)
    int n = bh >> 8, h = bh & 255;

    const float* ip = x + (((long long)n * C_) * HI + h) * WI + w0;
    #pragma unroll
    for (int k = 0; k < 4; k++) {
        int c = (k << 3) + wp;
        t[c][lane] = ip[(long long)c * (HI * WI) + lane];   // coalesced read
    }
    __syncthreads();

    float* op = (float*)g_nhwc4 + (((long long)n * HI + h) * WI + w0) * C_;
    #pragma unroll
    for (int k = 0; k < 4; k++) {
        int wl = (k << 3) + wp;
        op[wl * C_ + lane] = t[lane][wl];                   // coalesced write
    }
}

// ---------------- main fused kernel ----------------
__device__ __forceinline__ void axis_taps(float f, int U, int O,
                                          int& base, float w[3]) {
    float f0 = floorf(f);
    int   i0 = (int)f0;
    float wf = f - f0;

    w[0] = 0.f; w[1] = 0.f; w[2] = 0.f;
    base = 0;

    #pragma unroll
    for (int k = 0; k < 2; k++) {
        int   t  = i0 + k;
        float Wk = (k == 0) ? (1.0f - wf) : wf;
        Wk = (t >= 0 && t < U) ? Wk : 0.0f;          // zero-padding validity
        int tc = min(max(t, 0), U - 1);
        float s  = fmaxf((float)tc * 0.5f - 0.25f, 0.0f);  // upsample source
        int   o0 = (int)s;
        float wu = s - (float)o0;
        int   o1 = min(o0 + 1, O - 1);
        if (k == 0) base = o0;                       // taps are monotone
        w[o0 - base] += Wk * (1.0f - wu);
        w[o1 - base] += Wk * wu;
    }
}

// Predicated 128-bit load into FRESH zero-init b64 pair (2 movs).
// No memory request when w == 0; fma with w==0 contributes exactly 0.
__device__ __forceinline__ void pred_load2(unsigned long long& a,
                                           unsigned long long& b,
                                           const float4* addr, float w) {
    asm("{\n\t"
        ".reg .pred p;\n\t"
        "setp.ne.f32 p, %2, 0f00000000;\n\t"
        "mov.b64 %0, 0;\n\t"
        "mov.b64 %1, 0;\n\t"
        "@p ld.global.nc.v2.b64 {%0, %1}, [%3];\n\t"
        "}"
        : "=l"(a), "=l"(b)
        : "f"(w), "l"((const void*)addr));
}

#define PACK2(d, s)   asm("mov.b64 %0, {%1, %1};" : "=l"(d) : "f"(s))
#define FMA2(acc, t, w2) \
    asm("fma.rn.f32x2 %0, %1, %2, %0;" : "+l"(acc) : "l"(t), "l"(w2))
#define UNPACK2(lo, hi, s) \
    asm("mov.b64 {%0, %1}, %2;" : "=f"(lo), "=f"(hi) : "l"(s))

__global__ void __launch_bounds__(256, 4)
fused_gather_nhwc(const float* __restrict__ theta,
                  float* __restrict__ out) {
    __shared__ float obuf[8][C_][33];           // [warp][channel][point]
    // per-point tap table: [0..8]=wij row-major, [12..15]=ro4, [16..19]=co4
    __shared__ __align__(16) float tap[8][32][20];

    const unsigned FULL = 0xFFFFFFFFu;
    int w    = threadIdx.x >> 5;
    int lane = threadIdx.x & 31;
    int wid  = blockIdx.x * 8 + w;
    int n   = wid >> 13;                 // 8192 warps per image
    int r   = wid & 8191;
    int yo  = r >> 4;                    // 512 rows
    int xo0 = (r & 15) << 5;             // 16 x-segments of 32

    float* outp = out + ((long long)n * C_) * (HU * WU)
                      + (long long)yo * WU + xo0;

    const float* th = theta + n * 6;
    float t0 = __ldg(th + 0), t1 = __ldg(th + 1), t2 = __ldg(th + 2);
    float t3 = __ldg(th + 3), t4 = __ldg(th + 4), t5 = __ldg(th + 5);
    float gyn = (2.0f * (float)yo + 1.0f) / (float)HU - 1.0f;

    // ---- per-lane taps for point (xo0+lane, yo) -> SMEM table ----
    int z;
    {
        int xo = xo0 + lane;
        float gxn = (2.0f * (float)xo + 1.0f) / (float)WU - 1.0f;
        float gox = t0 * gxn + t1 * gyn + t2;
        float goy = t3 * gxn + t4 * gyn + t5;
        float ix = ((gox + 1.0f) * (float)WU - 1.0f) * 0.5f;
        float iy = ((goy + 1.0f) * (float)HU - 1.0f) * 0.5f;

        int by, bx;
        float wy[3], wx[3];
        axis_taps(iy, HU, HI, by, wy);
        axis_taps(ix, WU, WI, bx, wx);

        float* tp = tap[w][lane];
        *(float4*)(tp + 0) = make_float4(wy[0]*wx[0], wy[0]*wx[1],
                                         wy[0]*wx[2], wy[1]*wx[0]);
        *(float4*)(tp + 4) = make_float4(wy[1]*wx[1], wy[1]*wx[2],
                                         wy[2]*wx[0], wy[2]*wx[1]);
        tp[8] = wy[2]*wx[2];
        *(int4*)(tp + 12) = make_int4(min(by,     HI - 1) * (WI * (C_ / 4)),
                                      min(by + 1, HI - 1) * (WI * (C_ / 4)),
                                      min(by + 2, HI - 1) * (WI * (C_ / 4)), 0);
        *(int4*)(tp + 16) = make_int4(min(bx,     WI - 1) * (C_ / 4),
                                      min(bx + 1, WI - 1) * (C_ / 4),
                                      min(bx + 2, WI - 1) * (C_ / 4), 0);

        z = ((wy[0] + wy[1] + wy[2]) == 0.0f) ||
            ((wx[0] + wx[1] + wx[2]) == 0.0f);
    }
    __syncwarp();

    // ---- whole warp out of bounds: direct zero stores (STG.128) ----
    if (__all_sync(FULL, z)) {
        float4 zv = make_float4(0.f, 0.f, 0.f, 0.f);
        #pragma unroll
        for (int k = 0; k < 8; k++) {
            int c = (k << 2) | (lane >> 3);
            int piece = lane & 7;
            *(float4*)(outp + (long long)c * (HU * WU) + (piece << 2)) = zv;
        }
        return;
    }

    // ---- 8 passes of 4 points x 32 channels ----
    int g  = lane >> 3;                  // point within pass
    int lc = lane & 7;                   // channel quad
    const float4* xp = g_nhwc4 + (long long)n * (HI * WI * (C_ / 4)) + lc;

    for (int pass = 0; pass < 8; pass++) {
        int src = (pass << 2) | g;
        const float* tp = tap[w][src];
        // 5 broadcast LDS (quad-bank 5*src mod 8 distinct across g)
        float4 Wa = *(const float4*)(tp + 0);
        float4 Wb = *(const float4*)(tp + 4);
        float  w8 = tp[8];
        int4   RO = *(const int4*)(tp + 12);
        int4   CO = *(const int4*)(tp + 16);

        float wij[9] = {Wa.x, Wa.y, Wa.z, Wa.w, Wb.x, Wb.y, Wb.z, Wb.w, w8};

        unsigned long long acc01 = 0ull, acc23 = 0ull;
        unsigned long long t[10];

        // Wave 1: taps 0..4 (5 loads in flight), then FMA 0..4 in order
        pred_load2(t[0], t[1], xp + RO.x + CO.x, wij[0]);
        pred_load2(t[2], t[3], xp + RO.x + CO.y, wij[1]);
        pred_load2(t[4], t[5], xp + RO.x + CO.z, wij[2]);
        pred_load2(t[6], t[7], xp + RO.y + CO.x, wij[3]);
        pred_load2(t[8], t[9], xp + RO.y + CO.y, wij[4]);
        #pragma unroll
        for (int k = 0; k < 5; k++) {
            unsigned long long w2;
            PACK2(w2, wij[k]);
            FMA2(acc01, t[2 * k],     w2);
            FMA2(acc23, t[2 * k + 1], w2);
        }

        // Wave 2: taps 5..8 reuse t[0..7], then FMA 5..8 in order
        pred_load2(t[0], t[1], xp + RO.y + CO.z, wij[5]);
        pred_load2(t[2], t[3], xp + RO.z + CO.x, wij[6]);
        pred_load2(t[4], t[5], xp + RO.z + CO.y, wij[7]);
        pred_load2(t[6], t[7], xp + RO.z + CO.z, wij[8]);
        #pragma unroll
        for (int k = 0; k < 4; k++) {
            unsigned long long w2;
            PACK2(w2, wij[5 + k]);
            FMA2(acc01, t[2 * k],     w2);
            FMA2(acc23, t[2 * k + 1], w2);
        }

        float ax, ay, az, aw;
        UNPACK2(ax, ay, acc01);
        UNPACK2(az, aw, acc23);

        int p  = (pass << 2) | g;
        int cb = lc << 2;
        obuf[w][cb + 0][p] = ax;         // bank = (4lc+g)+const: conflict-free
        obuf[w][cb + 1][p] = ay;
        obuf[w][cb + 2][p] = az;
        obuf[w][cb + 3][p] = aw;
    }
    __syncwarp();

    // ---- NCHW stores: 8 x STG.128 (4 channel-rows / instruction) ----
    #pragma unroll
    for (int k = 0; k < 8; k++) {
        int c = (k << 2) | (lane >> 3);
        int piece = lane & 7;
        float4 v;
        v.x = obuf[w][c][(piece << 2) + 0];   // banks distinct across lanes
        v.y = obuf[w][c][(piece << 2) + 1];
        v.z = obuf[w][c][(piece << 2) + 2];
        v.w = obuf[w][c][(piece << 2) + 3];
        *(float4*)(outp + (long long)c * (HU * WU) + (piece << 2)) = v;
    }
}

extern "C" void kernel_launch(void* const* d_in, const int* in_sizes, int n_in,
                              void* d_out, int out_size) {
    const float* x     = (const float*)d_in[0];
    const float* theta = (const float*)d_in[1];
    float*       out   = (float*)d_out;

    dim3 tg(N_ * HI, WI / 32);           // (2048, 8) tiles of 32c x 32w
    transpose_nhwc<<<tg, 256>>>(x);

    // 65536 warps: one warp per 32-point output row segment (all 32 channels)
    fused_gather_nhwc<<<8192, 256>>>(theta, out);
}